// round 13
// baseline (speedup 1.0000x reference)
#include <cuda_runtime.h>
#include <cuda_fp16.h>
#include <math.h>

#define NN   50000
#define EE   800000
#define DIMM 128
#define ND   (NN*DIMM)
#define ND4  (ND/4)
#define LN_EPS 1e-5f
#define SCAN_BLOCKS ((NN + 1023) / 1024)   // 49
#define CNT_SHIFT 44
#define W_SCALE 16777216.0f                // 2^24
#define W_MASK ((1ULL << CNT_SHIFT) - 1ULL)

// ---------------- scratch ----------------
__device__ __align__(16) __half d_xcat[2*ND];
__device__ __align__(16) __half d_xh[ND];      // fp16 copy of x (written by GEMM y==0)
__device__ __align__(16) __half d_h[ND];       // GCN pre-LN (fp16 storage)
__device__ __align__(16) __half d_g[ND];       // GAT pre-LN (fp16 storage)
__device__ __align__(16) __half d_fused[ND];   // fused pre-final-LN (fp16 storage)
__device__ unsigned long long d_cntw[NN];      // [count:20 | degw fixed-point:44]
__device__ int    d_rowptr[NN+1];
__device__ int    d_erank[EE];                 // per-edge rank within its dst
__device__ float  d_dis[NN];
__device__ int2   d_csr[EE];               // {src, half2(dis[src]*ew, edge_attr)}
__device__ int    d_bsum[SCAN_BLOCKS];     // 0 = not ready, else tot+1
__device__ float  d_stats[8];              // [Sh,SSh,Sg,SSg,Sf,SSf]

__device__ __forceinline__ float gelu_exact(float v) {
    return 0.5f * v * (1.0f + erff(v * 0.7071067811865475f));
}

__device__ __forceinline__ float f2tf32f(float x) {
    unsigned r;
    asm("cvt.rna.tf32.f32 %0, %1;" : "=r"(r) : "f"(x));
    return __uint_as_float(r);
}

__device__ __forceinline__ void mma_tf32(float c[4], const unsigned a[4], const unsigned b[2]) {
    asm volatile(
        "mma.sync.aligned.m16n8k8.row.col.f32.tf32.tf32.f32 "
        "{%0,%1,%2,%3},{%4,%5,%6,%7},{%8,%9},{%0,%1,%2,%3};"
        : "+f"(c[0]), "+f"(c[1]), "+f"(c[2]), "+f"(c[3])
        : "r"(a[0]), "r"(a[1]), "r"(a[2]), "r"(a[3]), "r"(b[0]), "r"(b[1]));
}

__device__ __forceinline__ float4 hfpair(unsigned a, unsigned b) {
    __half2 x = *reinterpret_cast<const __half2*>(&a);
    __half2 y = *reinterpret_cast<const __half2*>(&b);
    float2 f0 = __half22float2(x);
    float2 f1 = __half22float2(y);
    return make_float4(f0.x, f0.y, f1.x, f1.y);
}

__device__ __forceinline__ uint2 pack_h4(float4 v) {
    __half2 p01 = __floats2half2_rn(v.x, v.y);
    __half2 p23 = __floats2half2_rn(v.z, v.w);
    return make_uint2(*reinterpret_cast<unsigned*>(&p01), *reinterpret_cast<unsigned*>(&p23));
}

// ---------------- K1: fused histogram: count + weighted degree in ONE atomic ----------------
__global__ void count_kernel(const int* __restrict__ ei, const float* __restrict__ ew) {
    int e = blockIdx.x * blockDim.x + threadIdx.x;
    if (e >= EE) return;
    int dv = ei[EE + e];
    unsigned long long pack = (1ULL << CNT_SHIFT)
                            + (unsigned long long)(ew[e] * W_SCALE + 0.5f);
    unsigned long long old = atomicAdd(&d_cntw[dv], pack);
    d_erank[e] = (int)(old >> CNT_SHIFT);     // rank of this edge within its dst
}

// ---------------- K2: single-kernel scan with decoupled lookback ----------------
__global__ void __launch_bounds__(1024) scan_kernel() {
    __shared__ int wsum[32];
    __shared__ int soff;
    int t = threadIdx.x, lane = t & 31, wid = t >> 5;
    int b = blockIdx.x;
    int idx = b * 1024 + t;
    if (b == 0 && t == 0) { d_stats[4] = 0.f; d_stats[5] = 0.f; }
    unsigned long long cw = (idx < NN) ? d_cntw[idx] : 0ULL;
    int v = (int)(cw >> CNT_SHIFT);
    int incl = v;
    #pragma unroll
    for (int o = 1; o < 32; o <<= 1) {
        int u = __shfl_up_sync(0xffffffffu, incl, o);
        if (lane >= o) incl += u;
    }
    if (lane == 31) wsum[wid] = incl;
    __syncthreads();
    if (wid == 0) {
        int wv = wsum[lane];
        #pragma unroll
        for (int o = 1; o < 32; o <<= 1) {
            int u = __shfl_up_sync(0xffffffffu, wv, o);
            if (lane >= o) wv += u;
        }
        wsum[lane] = wv;
    }
    __syncthreads();
    int my_incl = (wid ? wsum[wid - 1] : 0) + incl;
    if (t == 0) atomicExch(&d_bsum[b], wsum[31] + 1);   // publish block total
    if (wid == 0) {                                     // decoupled lookback
        int acc = 0;
        for (int p = lane; p < b; p += 32) {
            int val;
            while ((val = atomicAdd(&d_bsum[p], 0)) == 0) __nanosleep(40);
            acc += val - 1;
        }
        #pragma unroll
        for (int o = 16; o; o >>= 1) acc += __shfl_down_sync(0xffffffffu, acc, o);
        if (lane == 0) soff = acc;
    }
    __syncthreads();
    if (idx == 0) d_rowptr[0] = 0;
    if (idx >= NN) return;
    d_rowptr[idx + 1] = my_incl + soff;
    float dw = (float)((double)(cw & W_MASK) * (1.0 / (double)W_SCALE));
    d_dis[idx] = (dw > 0.f) ? rsqrtf(fmaxf(dw, 1e-30f)) : 0.f;
}

// ---------------- K3: scatter edges into packed 8B CSR (atomic-free) ----------------
__global__ void scatter_kernel(const int* __restrict__ ei, const float* __restrict__ ew,
                               const float* __restrict__ ea) {
    int e = blockIdx.x * blockDim.x + threadIdx.x;
    if (e >= EE) return;
    int s = ei[e];
    int dv = ei[EE + e];
    int p = d_rowptr[dv] + d_erank[e];
    float w = d_dis[s] * ew[e];
    __half2 pk = __floats2half2_rn(w, ea[e]);
    d_csr[p] = make_int2(s, *reinterpret_cast<int*>(&pk));
}

// ---------------- K4: dual GEMM, single-term TF32 MMA, fp16 epilogue ----------------
// blockIdx.y==0 also emits an fp16 copy of its x tile into d_xh (for fuse's residual)
#define ASTRIDE 136
__global__ void __launch_bounds__(256) gemm_tf32_kernel(const float* __restrict__ X,
                                                        const float* __restrict__ W0,
                                                        const float* __restrict__ W1,
                                                        const float* __restrict__ b1) {
    extern __shared__ float smem[];
    float* As = smem;                     // [128][136], tf32-rounded
    float* Ws = smem + 128 * ASTRIDE;     // [128][136], tf32-rounded
    const float* W = blockIdx.y ? W1 : W0;
    const int obase2 = blockIdx.y ? 2 : 0;

    int t = threadIdx.x;
    int row0 = blockIdx.x * 128;

    #pragma unroll
    for (int i = 0; i < 16; i++) {
        int idx = t + 256 * i;
        int r = idx >> 5;
        int c = (idx & 31) * 4;
        float4 xv = make_float4(0.f, 0.f, 0.f, 0.f);
        int grow = row0 + r;
        if (grow < NN) xv = *(const float4*)(X + grow * 128 + c);
        float4 wv = *(const float4*)(W + r * 128 + c);
        if (blockIdx.y == 0 && grow < NN) {
            ((uint2*)d_xh)[grow * 32 + (c >> 2)] = pack_h4(xv);   // fp16 x copy
        }
        xv.x = f2tf32f(xv.x); xv.y = f2tf32f(xv.y);
        xv.z = f2tf32f(xv.z); xv.w = f2tf32f(xv.w);
        wv.x = f2tf32f(wv.x); wv.y = f2tf32f(wv.y);
        wv.z = f2tf32f(wv.z); wv.w = f2tf32f(wv.w);
        *(float4*)(As + r * ASTRIDE + c) = xv;
        *(float4*)(Ws + r * ASTRIDE + c) = wv;
    }
    __syncthreads();

    int warp = t >> 5;
    int lane = t & 31;
    int gid = lane >> 2;
    int tid = lane & 3;
    int m0 = warp * 16;

    float c[16][4];
    #pragma unroll
    for (int nt = 0; nt < 16; nt++)
        #pragma unroll
        for (int j = 0; j < 4; j++) c[nt][j] = 0.f;

    #pragma unroll 2
    for (int ks = 0; ks < 16; ks++) {
        int k0 = ks * 8;
        const float* Ap = As + (m0 + gid) * ASTRIDE + k0 + tid;
        unsigned a[4];
        a[0] = __float_as_uint(Ap[0]);
        a[1] = __float_as_uint(Ap[8 * ASTRIDE]);
        a[2] = __float_as_uint(Ap[4]);
        a[3] = __float_as_uint(Ap[8 * ASTRIDE + 4]);
        const float* Bp = Ws + (k0 + tid) * ASTRIDE + gid;
        #pragma unroll
        for (int nt = 0; nt < 16; nt++) {
            unsigned b[2];
            b[0] = __float_as_uint(Bp[nt * 8]);
            b[1] = __float_as_uint(Bp[4 * ASTRIDE + nt * 8]);
            mma_tf32(c[nt], a, b);
        }
    }

    unsigned* xcat_u = (unsigned*)d_xcat;
    int rA = row0 + m0 + gid;
    int rB = rA + 8;
    #pragma unroll
    for (int nt = 0; nt < 16; nt++) {
        int col = nt * 8 + 2 * tid;
        int q = col >> 2;
        int word = tid & 1;
        int uoff = q * 4 + obase2 + word;
        float bv0 = 0.f, bv1 = 0.f;
        if (blockIdx.y) { bv0 = __ldg(b1 + col); bv1 = __ldg(b1 + col + 1); }
        if (rA < NN) {
            __half2 pv = __float22half2_rn(make_float2(c[nt][0] + bv0, c[nt][1] + bv1));
            xcat_u[rA * 128 + uoff] = *reinterpret_cast<unsigned*>(&pv);
        }
        if (rB < NN) {
            __half2 pv = __float22half2_rn(make_float2(c[nt][2] + bv0, c[nt][3] + bv1));
            xcat_u[rB * 128 + uoff] = *reinterpret_cast<unsigned*>(&pv);
        }
    }
}

// ---------------- K5: warp-per-dst aggregation + fused LN stats ----------------
__global__ void __launch_bounds__(256) agg_kernel(const float* __restrict__ b_gcn,
                                                  const float* __restrict__ b_gat,
                                                  const float* __restrict__ W_edge,
                                                  const float* __restrict__ att) {
    int gw = (blockIdx.x * blockDim.x + threadIdx.x) >> 5;
    int lane = threadIdx.x & 31;
    float s_h = 0.f, ss_h = 0.f, s_g = 0.f, ss_g = 0.f;

    if (gw < NN) {
        int r0 = d_rowptr[gw];
        int r1 = d_rowptr[gw + 1];
        float disd = d_dis[gw];

        const uint4* cat = (const uint4*)d_xcat;   // node row = 32 uint4
        uint4 ud = cat[gw * 32 + lane];
        float4 xld = hfpair(ud.z, ud.w);
        float4 we  = __ldg(((const float4*)W_edge) + lane);
        float4 at  = __ldg(((const float4*)att) + lane);

        float4 hacc = make_float4(0.f, 0.f, 0.f, 0.f);
        float4 acc  = make_float4(0.f, 0.f, 0.f, 0.f);
        float m = -INFINITY, dsum = 0.f;

        int2 ce = (r0 < r1) ? __ldg(&d_csr[r0]) : make_int2(0, 0);
        for (int p = r0; p < r1; ++p) {
            int2 cn = (p + 1 < r1) ? __ldg(&d_csr[p + 1]) : ce;
            int src = ce.x;
            float2 wea = __half22float2(*reinterpret_cast<const __half2*>(&ce.y));
            float cw  = wea.x * disd;
            float eav = wea.y;
            uint4 us = cat[src * 32 + lane];
            ce = cn;
            float4 xws = hfpair(us.x, us.y);
            float4 xls = hfpair(us.z, us.w);

            hacc.x += cw * xws.x; hacc.y += cw * xws.y;
            hacc.z += cw * xws.z; hacc.w += cw * xws.w;

            float4 z;
            z.x = xld.x + xls.x + eav * we.x;
            z.y = xld.y + xls.y + eav * we.y;
            z.z = xld.z + xls.z + eav * we.z;
            z.w = xld.w + xls.w + eav * we.w;
            z.x = z.x > 0.f ? z.x : 0.2f * z.x;
            z.y = z.y > 0.f ? z.y : 0.2f * z.y;
            z.z = z.z > 0.f ? z.z : 0.2f * z.z;
            z.w = z.w > 0.f ? z.w : 0.2f * z.w;
            float part = z.x * at.x + z.y * at.y + z.z * at.z + z.w * at.w;
            part += __shfl_xor_sync(0xffffffffu, part, 1);
            part += __shfl_xor_sync(0xffffffffu, part, 2);
            part += __shfl_xor_sync(0xffffffffu, part, 4);  // per-head logit

            float mn = fmaxf(m, part);
            float sc = __expf(m - mn);
            float pe = __expf(part - mn);
            dsum = dsum * sc + pe;
            acc.x = acc.x * sc + pe * xls.x;
            acc.y = acc.y * sc + pe * xls.y;
            acc.z = acc.z * sc + pe * xls.z;
            acc.w = acc.w * sc + pe * xls.w;
            m = mn;
        }

        float inv = 1.0f / (dsum + 1e-16f);
        float4 bc = __ldg(((const float4*)b_gcn) + lane);
        float4 bg = __ldg(((const float4*)b_gat) + lane);
        float4 ho = make_float4(hacc.x + bc.x, hacc.y + bc.y, hacc.z + bc.z, hacc.w + bc.w);
        float4 go = make_float4(acc.x * inv + bg.x, acc.y * inv + bg.y,
                                acc.z * inv + bg.z, acc.w * inv + bg.w);

        uint2 hw = pack_h4(ho);
        uint2 gww = pack_h4(go);
        ((uint2*)d_h)[gw * 32 + lane] = hw;
        ((uint2*)d_g)[gw * 32 + lane] = gww;
        float4 hr = hfpair(hw.x, hw.y);
        float4 gr = hfpair(gww.x, gww.y);

        s_h  = hr.x + hr.y + hr.z + hr.w;
        ss_h = hr.x * hr.x + hr.y * hr.y + hr.z * hr.z + hr.w * hr.w;
        s_g  = gr.x + gr.y + gr.z + gr.w;
        ss_g = gr.x * gr.x + gr.y * gr.y + gr.z * gr.z + gr.w * gr.w;
    }

    #pragma unroll
    for (int o = 16; o; o >>= 1) {
        s_h  += __shfl_down_sync(0xffffffffu, s_h, o);
        ss_h += __shfl_down_sync(0xffffffffu, ss_h, o);
        s_g  += __shfl_down_sync(0xffffffffu, s_g, o);
        ss_g += __shfl_down_sync(0xffffffffu, ss_g, o);
    }
    __shared__ float sm[4][8];
    int wid = threadIdx.x >> 5;
    if (lane == 0) { sm[0][wid] = s_h; sm[1][wid] = ss_h; sm[2][wid] = s_g; sm[3][wid] = ss_g; }
    __syncthreads();
    if (threadIdx.x == 0) {
        float a = 0.f, b = 0.f, cc = 0.f, d = 0.f;
        #pragma unroll
        for (int i = 0; i < 8; i++) { a += sm[0][i]; b += sm[1][i]; cc += sm[2][i]; d += sm[3][i]; }
        atomicAdd(&d_stats[0], a);
        atomicAdd(&d_stats[1], b);
        atomicAdd(&d_stats[2], cc);
        atomicAdd(&d_stats[3], d);
    }
}

// ---------------- K6: LN+gelu both branches, residual (fp16 x), fuse; stats ----------------
// also re-zeroes d_cntw/d_bsum for the next call
__global__ void fuse_kernel(const float* __restrict__ gcn_nw, const float* __restrict__ gcn_nb,
                            const float* __restrict__ gat_nw, const float* __restrict__ gat_nb,
                            const float* __restrict__ alpha) {
    const float M = (float)ND;
    float mu_h = d_stats[0] / M;
    float inv_h = 1.0f / (sqrtf(fmaxf(d_stats[1] / M - mu_h * mu_h, 0.f)) + LN_EPS);
    float mu_g = d_stats[2] / M;
    float inv_g = 1.0f / (sqrtf(fmaxf(d_stats[3] / M - mu_g * mu_g, 0.f)) + LN_EPS);
    float a0 = alpha[0], a1 = alpha[1];
    float mx = fmaxf(a0, a1);
    float e0 = expf(a0 - mx), e1 = expf(a1 - mx);
    float w0 = e0 / (e0 + e1), w1 = e1 / (e0 + e1);

    int gid0 = blockIdx.x * blockDim.x + threadIdx.x;
    int gstride = gridDim.x * blockDim.x;
    for (int i = gid0; i < NN; i += gstride) d_cntw[i] = 0ULL;
    if (gid0 < SCAN_BLOCKS) d_bsum[gid0] = 0;

    float sf = 0.f, ssf = 0.f;
    const uint2* xh2 = (const uint2*)d_xh;
    const uint2* h2 = (const uint2*)d_h;
    const uint2* g2 = (const uint2*)d_g;
    uint2* f2 = (uint2*)d_fused;
    for (int i = gid0; i < ND4; i += gstride) {
        int c4 = i & 31;
        float4 nwh = __ldg(((const float4*)gcn_nw) + c4);
        float4 nbh = __ldg(((const float4*)gcn_nb) + c4);
        float4 nwg = __ldg(((const float4*)gat_nw) + c4);
        float4 nbg = __ldg(((const float4*)gat_nb) + c4);
        uint2 hu = h2[i], gu = g2[i], xu = xh2[i];
        float4 hv = hfpair(hu.x, hu.y);
        float4 gv = hfpair(gu.x, gu.y);
        float4 xv = hfpair(xu.x, xu.y);
        float4 fv;
        float t, u;
        t = gelu_exact((hv.x - mu_h) * inv_h * nwh.x + nbh.x);
        u = gelu_exact((gv.x - mu_g) * inv_g * nwg.x + nbg.x);
        fv.x = w0 * (xv.x + t) + w1 * (xv.x + u);
        t = gelu_exact((hv.y - mu_h) * inv_h * nwh.y + nbh.y);
        u = gelu_exact((gv.y - mu_g) * inv_g * nwg.y + nbg.y);
        fv.y = w0 * (xv.y + t) + w1 * (xv.y + u);
        t = gelu_exact((hv.z - mu_h) * inv_h * nwh.z + nbh.z);
        u = gelu_exact((gv.z - mu_g) * inv_g * nwg.z + nbg.z);
        fv.z = w0 * (xv.z + t) + w1 * (xv.z + u);
        t = gelu_exact((hv.w - mu_h) * inv_h * nwh.w + nbh.w);
        u = gelu_exact((gv.w - mu_g) * inv_g * nwg.w + nbg.w);
        fv.w = w0 * (xv.w + t) + w1 * (xv.w + u);

        uint2 fw = pack_h4(fv);
        f2[i] = fw;
        float4 fr = hfpair(fw.x, fw.y);
        sf  += fr.x + fr.y + fr.z + fr.w;
        ssf += fr.x * fr.x + fr.y * fr.y + fr.z * fr.z + fr.w * fr.w;
    }
    #pragma unroll
    for (int o = 16; o; o >>= 1) {
        sf  += __shfl_down_sync(0xffffffffu, sf, o);
        ssf += __shfl_down_sync(0xffffffffu, ssf, o);
    }
    __shared__ float sm[2][8];
    int wid = threadIdx.x >> 5, lane = threadIdx.x & 31;
    if (lane == 0) { sm[0][wid] = sf; sm[1][wid] = ssf; }
    __syncthreads();
    if (threadIdx.x == 0) {
        float a = 0.f, b = 0.f;
        #pragma unroll
        for (int i = 0; i < 8; i++) { a += sm[0][i]; b += sm[1][i]; }
        atomicAdd(&d_stats[4], a);
        atomicAdd(&d_stats[5], b);
    }
}

// ---------------- K7: final LN + gelu -> out; re-zero stats[0..3] for next call ----------------
__global__ void out_kernel(const float* __restrict__ onw, const float* __restrict__ onb,
                           float* __restrict__ out) {
    const float M = (float)ND;
    float mu = d_stats[4] / M;
    float inv = 1.0f / (sqrtf(fmaxf(d_stats[5] / M - mu * mu, 0.f)) + LN_EPS);
    if (blockIdx.x == 0 && threadIdx.x < 4) d_stats[threadIdx.x] = 0.f;
    const uint2* f2 = (const uint2*)d_fused;
    float4* o4 = (float4*)out;
    for (int i = blockIdx.x * blockDim.x + threadIdx.x; i < ND4; i += gridDim.x * blockDim.x) {
        int c4 = i & 31;
        float4 nw = __ldg(((const float4*)onw) + c4);
        float4 nb = __ldg(((const float4*)onb) + c4);
        uint2 fu = f2[i];
        float4 fv = hfpair(fu.x, fu.y);
        float4 ov;
        ov.x = gelu_exact((fv.x - mu) * inv * nw.x + nb.x);
        ov.y = gelu_exact((fv.y - mu) * inv * nw.y + nb.y);
        ov.z = gelu_exact((fv.z - mu) * inv * nw.z + nb.z);
        ov.w = gelu_exact((fv.w - mu) * inv * nw.w + nb.w);
        o4[i] = ov;
    }
}

// ---------------- launch ----------------
extern "C" void kernel_launch(void* const* d_in, const int* in_sizes, int n_in,
                              void* d_out, int out_size) {
    const float* x      = (const float*)d_in[0];
    const int*   ei     = (const int*)d_in[1];
    const float* ew     = (const float*)d_in[2];
    const float* ea     = (const float*)d_in[3];
    const float* W_gcn  = (const float*)d_in[4];
    const float* b_gcn  = (const float*)d_in[5];
    const float* W_l    = (const float*)d_in[6];
    const float* b_l    = (const float*)d_in[7];
    const float* W_edge = (const float*)d_in[8];
    const float* att    = (const float*)d_in[9];
    const float* b_gat  = (const float*)d_in[10];
    const float* gcn_nw = (const float*)d_in[11];
    const float* gcn_nb = (const float*)d_in[12];
    const float* gat_nw = (const float*)d_in[13];
    const float* gat_nb = (const float*)d_in[14];
    const float* out_nw = (const float*)d_in[15];
    const float* out_nb = (const float*)d_in[16];
    const float* alpha  = (const float*)d_in[17];
    float* out = (float*)d_out;

    static cudaStream_t s_side = 0;
    static cudaEvent_t ev_fork = 0, ev_join = 0;
    if (!s_side) {
        cudaStreamCreateWithFlags(&s_side, cudaStreamNonBlocking);
        cudaEventCreateWithFlags(&ev_fork, cudaEventDisableTiming);
        cudaEventCreateWithFlags(&ev_join, cudaEventDisableTiming);
    }

    const int GEMM_SMEM = 2 * 128 * ASTRIDE * sizeof(float);  // 139264 B
    cudaFuncSetAttribute(gemm_tf32_kernel, cudaFuncAttributeMaxDynamicSharedMemorySize, GEMM_SMEM);

    // fork: GEMM on side stream, CSR build on main stream
    cudaEventRecord(ev_fork, 0);
    cudaStreamWaitEvent(s_side, ev_fork, 0);
    dim3 gg((NN + 127) / 128, 2);
    gemm_tf32_kernel<<<gg, 256, GEMM_SMEM, s_side>>>(x, W_gcn, W_l, b_l);
    cudaEventRecord(ev_join, s_side);

    count_kernel<<<(EE + 255) / 256, 256>>>(ei, ew);
    scan_kernel<<<SCAN_BLOCKS, 1024>>>();
    scatter_kernel<<<(EE + 255) / 256, 256>>>(ei, ew, ea);

    // join: agg needs both CSR and GEMM outputs
    cudaStreamWaitEvent(0, ev_join, 0);
    agg_kernel<<<(NN + 7) / 8, 256>>>(b_gcn, b_gat, W_edge, att);
    fuse_kernel<<<1480, 256>>>(gcn_nw, gcn_nb, gat_nw, gat_nb, alpha);
    out_kernel<<<1480, 256>>>(out_nw, out_nb, out);
}

// round 14
// speedup vs baseline: 1.0715x; 1.0715x over previous
#include <cuda_runtime.h>
#include <cuda_fp16.h>
#include <math.h>

#define NN   50000
#define EE   800000
#define DIMM 128
#define ND   (NN*DIMM)
#define ND4  (ND/4)
#define LN_EPS 1e-5f
#define SCAN_BLOCKS ((NN + 1023) / 1024)   // 49
#define CNT_SHIFT 44
#define W_SCALE 16777216.0f                // 2^24
#define W_MASK ((1ULL << CNT_SHIFT) - 1ULL)

// ---------------- scratch ----------------
__device__ __align__(16) __half d_xcat[2*ND];
__device__ __align__(16) __half d_h[ND];       // GCN pre-LN (fp16 storage)
__device__ __align__(16) __half d_g[ND];       // GAT pre-LN (fp16 storage)
__device__ __align__(16) __half d_fused[ND];   // fused pre-final-LN (fp16 storage)
__device__ unsigned long long d_cntw[NN];      // [count:20 | degw fixed-point:44]
__device__ int    d_rowptr[NN+1];
__device__ int    d_erank[EE];                 // per-edge rank within its dst
__device__ float  d_dis[NN];
__device__ int2   d_csr[EE];               // {src, half2(dis[src]*ew, edge_attr)}
__device__ int    d_bsum[SCAN_BLOCKS];     // 0 = not ready, else tot+1
__device__ float  d_stats[8];              // [Sh,SSh,Sg,SSg,Sf,SSf]

__device__ __forceinline__ float gelu_exact(float v) {
    return 0.5f * v * (1.0f + erff(v * 0.7071067811865475f));
}

__device__ __forceinline__ float f2tf32f(float x) {
    unsigned r;
    asm("cvt.rna.tf32.f32 %0, %1;" : "=r"(r) : "f"(x));
    return __uint_as_float(r);
}

__device__ __forceinline__ void mma_tf32(float c[4], const unsigned a[4], const unsigned b[2]) {
    asm volatile(
        "mma.sync.aligned.m16n8k8.row.col.f32.tf32.tf32.f32 "
        "{%0,%1,%2,%3},{%4,%5,%6,%7},{%8,%9},{%0,%1,%2,%3};"
        : "+f"(c[0]), "+f"(c[1]), "+f"(c[2]), "+f"(c[3])
        : "r"(a[0]), "r"(a[1]), "r"(a[2]), "r"(a[3]), "r"(b[0]), "r"(b[1]));
}

__device__ __forceinline__ float4 hfpair(unsigned a, unsigned b) {
    __half2 x = *reinterpret_cast<const __half2*>(&a);
    __half2 y = *reinterpret_cast<const __half2*>(&b);
    float2 f0 = __half22float2(x);
    float2 f1 = __half22float2(y);
    return make_float4(f0.x, f0.y, f1.x, f1.y);
}

__device__ __forceinline__ uint2 pack_h4(float4 v) {
    __half2 p01 = __floats2half2_rn(v.x, v.y);
    __half2 p23 = __floats2half2_rn(v.z, v.w);
    return make_uint2(*reinterpret_cast<unsigned*>(&p01), *reinterpret_cast<unsigned*>(&p23));
}

// ---------------- K1: fused histogram: count + weighted degree in ONE atomic ----------------
__global__ void count_kernel(const int* __restrict__ ei, const float* __restrict__ ew) {
    int e = blockIdx.x * blockDim.x + threadIdx.x;
    if (e >= EE) return;
    int dv = ei[EE + e];
    unsigned long long pack = (1ULL << CNT_SHIFT)
                            + (unsigned long long)(ew[e] * W_SCALE + 0.5f);
    unsigned long long old = atomicAdd(&d_cntw[dv], pack);
    d_erank[e] = (int)(old >> CNT_SHIFT);     // rank of this edge within its dst
}

// ---------------- K2: single-kernel scan with decoupled lookback ----------------
__global__ void __launch_bounds__(1024) scan_kernel() {
    __shared__ int wsum[32];
    __shared__ int soff;
    int t = threadIdx.x, lane = t & 31, wid = t >> 5;
    int b = blockIdx.x;
    int idx = b * 1024 + t;
    if (b == 0 && t == 0) { d_stats[4] = 0.f; d_stats[5] = 0.f; }
    unsigned long long cw = (idx < NN) ? d_cntw[idx] : 0ULL;
    int v = (int)(cw >> CNT_SHIFT);
    int incl = v;
    #pragma unroll
    for (int o = 1; o < 32; o <<= 1) {
        int u = __shfl_up_sync(0xffffffffu, incl, o);
        if (lane >= o) incl += u;
    }
    if (lane == 31) wsum[wid] = incl;
    __syncthreads();
    if (wid == 0) {
        int wv = wsum[lane];
        #pragma unroll
        for (int o = 1; o < 32; o <<= 1) {
            int u = __shfl_up_sync(0xffffffffu, wv, o);
            if (lane >= o) wv += u;
        }
        wsum[lane] = wv;
    }
    __syncthreads();
    int my_incl = (wid ? wsum[wid - 1] : 0) + incl;
    if (t == 0) atomicExch(&d_bsum[b], wsum[31] + 1);   // publish block total
    if (wid == 0) {                                     // decoupled lookback
        int acc = 0;
        for (int p = lane; p < b; p += 32) {
            int val;
            while ((val = atomicAdd(&d_bsum[p], 0)) == 0) __nanosleep(40);
            acc += val - 1;
        }
        #pragma unroll
        for (int o = 16; o; o >>= 1) acc += __shfl_down_sync(0xffffffffu, acc, o);
        if (lane == 0) soff = acc;
    }
    __syncthreads();
    if (idx == 0) d_rowptr[0] = 0;
    if (idx >= NN) return;
    d_rowptr[idx + 1] = my_incl + soff;
    float dw = (float)((double)(cw & W_MASK) * (1.0 / (double)W_SCALE));
    d_dis[idx] = (dw > 0.f) ? rsqrtf(fmaxf(dw, 1e-30f)) : 0.f;
}

// ---------------- K3: scatter edges into packed 8B CSR (atomic-free) ----------------
__global__ void scatter_kernel(const int* __restrict__ ei, const float* __restrict__ ew,
                               const float* __restrict__ ea) {
    int e = blockIdx.x * blockDim.x + threadIdx.x;
    if (e >= EE) return;
    int s = ei[e];
    int dv = ei[EE + e];
    int p = d_rowptr[dv] + d_erank[e];
    float w = d_dis[s] * ew[e];
    __half2 pk = __floats2half2_rn(w, ea[e]);
    d_csr[p] = make_int2(s, *reinterpret_cast<int*>(&pk));
}

// ---------------- K4: dual GEMM, single-term TF32 MMA, fp16 epilogue ----------------
#define ASTRIDE 136
__global__ void __launch_bounds__(256) gemm_tf32_kernel(const float* __restrict__ X,
                                                        const float* __restrict__ W0,
                                                        const float* __restrict__ W1,
                                                        const float* __restrict__ b1) {
    extern __shared__ float smem[];
    float* As = smem;                     // [128][136], tf32-rounded
    float* Ws = smem + 128 * ASTRIDE;     // [128][136], tf32-rounded
    const float* W = blockIdx.y ? W1 : W0;
    const int obase2 = blockIdx.y ? 2 : 0;

    int t = threadIdx.x;
    int row0 = blockIdx.x * 128;

    #pragma unroll
    for (int i = 0; i < 16; i++) {
        int idx = t + 256 * i;
        int r = idx >> 5;
        int c = (idx & 31) * 4;
        float4 xv = make_float4(0.f, 0.f, 0.f, 0.f);
        int grow = row0 + r;
        if (grow < NN) xv = *(const float4*)(X + grow * 128 + c);
        float4 wv = *(const float4*)(W + r * 128 + c);
        xv.x = f2tf32f(xv.x); xv.y = f2tf32f(xv.y);
        xv.z = f2tf32f(xv.z); xv.w = f2tf32f(xv.w);
        wv.x = f2tf32f(wv.x); wv.y = f2tf32f(wv.y);
        wv.z = f2tf32f(wv.z); wv.w = f2tf32f(wv.w);
        *(float4*)(As + r * ASTRIDE + c) = xv;
        *(float4*)(Ws + r * ASTRIDE + c) = wv;
    }
    __syncthreads();

    int warp = t >> 5;
    int lane = t & 31;
    int gid = lane >> 2;
    int tid = lane & 3;
    int m0 = warp * 16;

    float c[16][4];
    #pragma unroll
    for (int nt = 0; nt < 16; nt++)
        #pragma unroll
        for (int j = 0; j < 4; j++) c[nt][j] = 0.f;

    #pragma unroll 2
    for (int ks = 0; ks < 16; ks++) {
        int k0 = ks * 8;
        const float* Ap = As + (m0 + gid) * ASTRIDE + k0 + tid;
        unsigned a[4];
        a[0] = __float_as_uint(Ap[0]);
        a[1] = __float_as_uint(Ap[8 * ASTRIDE]);
        a[2] = __float_as_uint(Ap[4]);
        a[3] = __float_as_uint(Ap[8 * ASTRIDE + 4]);
        const float* Bp = Ws + (k0 + tid) * ASTRIDE + gid;
        #pragma unroll
        for (int nt = 0; nt < 16; nt++) {
            unsigned b[2];
            b[0] = __float_as_uint(Bp[nt * 8]);
            b[1] = __float_as_uint(Bp[4 * ASTRIDE + nt * 8]);
            mma_tf32(c[nt], a, b);
        }
    }

    unsigned* xcat_u = (unsigned*)d_xcat;
    int rA = row0 + m0 + gid;
    int rB = rA + 8;
    #pragma unroll
    for (int nt = 0; nt < 16; nt++) {
        int col = nt * 8 + 2 * tid;
        int q = col >> 2;
        int word = tid & 1;
        int uoff = q * 4 + obase2 + word;
        float bv0 = 0.f, bv1 = 0.f;
        if (blockIdx.y) { bv0 = __ldg(b1 + col); bv1 = __ldg(b1 + col + 1); }
        if (rA < NN) {
            __half2 pv = __float22half2_rn(make_float2(c[nt][0] + bv0, c[nt][1] + bv1));
            xcat_u[rA * 128 + uoff] = *reinterpret_cast<unsigned*>(&pv);
        }
        if (rB < NN) {
            __half2 pv = __float22half2_rn(make_float2(c[nt][2] + bv0, c[nt][3] + bv1));
            xcat_u[rB * 128 + uoff] = *reinterpret_cast<unsigned*>(&pv);
        }
    }
}

// ---------------- K5: warp-per-dst aggregation, 2 edges/iter + fused LN stats ----------------
__global__ void __launch_bounds__(256) agg_kernel(const float* __restrict__ b_gcn,
                                                  const float* __restrict__ b_gat,
                                                  const float* __restrict__ W_edge,
                                                  const float* __restrict__ att) {
    int gw = (blockIdx.x * blockDim.x + threadIdx.x) >> 5;
    int lane = threadIdx.x & 31;
    float s_h = 0.f, ss_h = 0.f, s_g = 0.f, ss_g = 0.f;

    if (gw < NN) {
        int r0 = d_rowptr[gw];
        int r1 = d_rowptr[gw + 1];
        float disd = d_dis[gw];

        const uint4* cat = (const uint4*)d_xcat;   // node row = 32 uint4
        uint4 ud = cat[gw * 32 + lane];
        float4 xld = hfpair(ud.z, ud.w);
        float4 we  = __ldg(((const float4*)W_edge) + lane);
        float4 at  = __ldg(((const float4*)att) + lane);

        float4 hacc = make_float4(0.f, 0.f, 0.f, 0.f);
        float4 acc  = make_float4(0.f, 0.f, 0.f, 0.f);
        float m = -INFINITY, dsum = 0.f;

        int p = r0;
        // paired loop: 2 edges per iteration (pairwise online-softmax merge)
        for (; p + 1 < r1; p += 2) {
            int2 c0 = __ldg(&d_csr[p]);
            int2 c1 = __ldg(&d_csr[p + 1]);
            uint4 u0 = cat[c0.x * 32 + lane];
            uint4 u1 = cat[c1.x * 32 + lane];

            float2 w0p = __half22float2(*reinterpret_cast<const __half2*>(&c0.y));
            float2 w1p = __half22float2(*reinterpret_cast<const __half2*>(&c1.y));
            float cw0 = w0p.x * disd, ea0 = w0p.y;
            float cw1 = w1p.x * disd, ea1 = w1p.y;

            float4 xw0 = hfpair(u0.x, u0.y);
            float4 xl0 = hfpair(u0.z, u0.w);
            float4 xw1 = hfpair(u1.x, u1.y);
            float4 xl1 = hfpair(u1.z, u1.w);

            hacc.x += cw0 * xw0.x + cw1 * xw1.x;
            hacc.y += cw0 * xw0.y + cw1 * xw1.y;
            hacc.z += cw0 * xw0.z + cw1 * xw1.z;
            hacc.w += cw0 * xw0.w + cw1 * xw1.w;

            float4 z0, z1;
            z0.x = xld.x + xl0.x + ea0 * we.x;  z1.x = xld.x + xl1.x + ea1 * we.x;
            z0.y = xld.y + xl0.y + ea0 * we.y;  z1.y = xld.y + xl1.y + ea1 * we.y;
            z0.z = xld.z + xl0.z + ea0 * we.z;  z1.z = xld.z + xl1.z + ea1 * we.z;
            z0.w = xld.w + xl0.w + ea0 * we.w;  z1.w = xld.w + xl1.w + ea1 * we.w;
            z0.x = z0.x > 0.f ? z0.x : 0.2f * z0.x;  z1.x = z1.x > 0.f ? z1.x : 0.2f * z1.x;
            z0.y = z0.y > 0.f ? z0.y : 0.2f * z0.y;  z1.y = z1.y > 0.f ? z1.y : 0.2f * z1.y;
            z0.z = z0.z > 0.f ? z0.z : 0.2f * z0.z;  z1.z = z1.z > 0.f ? z1.z : 0.2f * z1.z;
            z0.w = z0.w > 0.f ? z0.w : 0.2f * z0.w;  z1.w = z1.w > 0.f ? z1.w : 0.2f * z1.w;

            float p0 = z0.x * at.x + z0.y * at.y + z0.z * at.z + z0.w * at.w;
            float p1 = z1.x * at.x + z1.y * at.y + z1.z * at.z + z1.w * at.w;
            p0 += __shfl_xor_sync(0xffffffffu, p0, 1);
            p1 += __shfl_xor_sync(0xffffffffu, p1, 1);
            p0 += __shfl_xor_sync(0xffffffffu, p0, 2);
            p1 += __shfl_xor_sync(0xffffffffu, p1, 2);
            p0 += __shfl_xor_sync(0xffffffffu, p0, 4);
            p1 += __shfl_xor_sync(0xffffffffu, p1, 4);   // per-head logits

            float mn = fmaxf(m, fmaxf(p0, p1));
            float sc = __expf(m - mn);
            float e0 = __expf(p0 - mn);
            float e1 = __expf(p1 - mn);
            dsum = dsum * sc + e0 + e1;
            acc.x = acc.x * sc + e0 * xl0.x + e1 * xl1.x;
            acc.y = acc.y * sc + e0 * xl0.y + e1 * xl1.y;
            acc.z = acc.z * sc + e0 * xl0.z + e1 * xl1.z;
            acc.w = acc.w * sc + e0 * xl0.w + e1 * xl1.w;
            m = mn;
        }
        // tail (odd edge count)
        if (p < r1) {
            int2 ce = __ldg(&d_csr[p]);
            float2 wea = __half22float2(*reinterpret_cast<const __half2*>(&ce.y));
            float cw  = wea.x * disd;
            float eav = wea.y;
            uint4 us = cat[ce.x * 32 + lane];
            float4 xws = hfpair(us.x, us.y);
            float4 xls = hfpair(us.z, us.w);

            hacc.x += cw * xws.x; hacc.y += cw * xws.y;
            hacc.z += cw * xws.z; hacc.w += cw * xws.w;

            float4 z;
            z.x = xld.x + xls.x + eav * we.x;
            z.y = xld.y + xls.y + eav * we.y;
            z.z = xld.z + xls.z + eav * we.z;
            z.w = xld.w + xls.w + eav * we.w;
            z.x = z.x > 0.f ? z.x : 0.2f * z.x;
            z.y = z.y > 0.f ? z.y : 0.2f * z.y;
            z.z = z.z > 0.f ? z.z : 0.2f * z.z;
            z.w = z.w > 0.f ? z.w : 0.2f * z.w;
            float part = z.x * at.x + z.y * at.y + z.z * at.z + z.w * at.w;
            part += __shfl_xor_sync(0xffffffffu, part, 1);
            part += __shfl_xor_sync(0xffffffffu, part, 2);
            part += __shfl_xor_sync(0xffffffffu, part, 4);

            float mn = fmaxf(m, part);
            float sc = __expf(m - mn);
            float pe = __expf(part - mn);
            dsum = dsum * sc + pe;
            acc.x = acc.x * sc + pe * xls.x;
            acc.y = acc.y * sc + pe * xls.y;
            acc.z = acc.z * sc + pe * xls.z;
            acc.w = acc.w * sc + pe * xls.w;
            m = mn;
        }

        float inv = 1.0f / (dsum + 1e-16f);
        float4 bc = __ldg(((const float4*)b_gcn) + lane);
        float4 bg = __ldg(((const float4*)b_gat) + lane);
        float4 ho = make_float4(hacc.x + bc.x, hacc.y + bc.y, hacc.z + bc.z, hacc.w + bc.w);
        float4 go = make_float4(acc.x * inv + bg.x, acc.y * inv + bg.y,
                                acc.z * inv + bg.z, acc.w * inv + bg.w);

        uint2 hw = pack_h4(ho);
        uint2 gww = pack_h4(go);
        ((uint2*)d_h)[gw * 32 + lane] = hw;
        ((uint2*)d_g)[gw * 32 + lane] = gww;
        float4 hr = hfpair(hw.x, hw.y);
        float4 gr = hfpair(gww.x, gww.y);

        s_h  = hr.x + hr.y + hr.z + hr.w;
        ss_h = hr.x * hr.x + hr.y * hr.y + hr.z * hr.z + hr.w * hr.w;
        s_g  = gr.x + gr.y + gr.z + gr.w;
        ss_g = gr.x * gr.x + gr.y * gr.y + gr.z * gr.z + gr.w * gr.w;
    }

    #pragma unroll
    for (int o = 16; o; o >>= 1) {
        s_h  += __shfl_down_sync(0xffffffffu, s_h, o);
        ss_h += __shfl_down_sync(0xffffffffu, ss_h, o);
        s_g  += __shfl_down_sync(0xffffffffu, s_g, o);
        ss_g += __shfl_down_sync(0xffffffffu, ss_g, o);
    }
    __shared__ float sm[4][8];
    int wid = threadIdx.x >> 5;
    if (lane == 0) { sm[0][wid] = s_h; sm[1][wid] = ss_h; sm[2][wid] = s_g; sm[3][wid] = ss_g; }
    __syncthreads();
    if (threadIdx.x == 0) {
        float a = 0.f, b = 0.f, cc = 0.f, d = 0.f;
        #pragma unroll
        for (int i = 0; i < 8; i++) { a += sm[0][i]; b += sm[1][i]; cc += sm[2][i]; d += sm[3][i]; }
        atomicAdd(&d_stats[0], a);
        atomicAdd(&d_stats[1], b);
        atomicAdd(&d_stats[2], cc);
        atomicAdd(&d_stats[3], d);
    }
}

// ---------------- K6: LN+gelu both branches, residual, fuse; stats of fused ----------------
// also re-zeroes d_cntw/d_bsum for the next call
__global__ void fuse_kernel(const float* __restrict__ x,
                            const float* __restrict__ gcn_nw, const float* __restrict__ gcn_nb,
                            const float* __restrict__ gat_nw, const float* __restrict__ gat_nb,
                            const float* __restrict__ alpha) {
    const float M = (float)ND;
    float mu_h = d_stats[0] / M;
    float inv_h = 1.0f / (sqrtf(fmaxf(d_stats[1] / M - mu_h * mu_h, 0.f)) + LN_EPS);
    float mu_g = d_stats[2] / M;
    float inv_g = 1.0f / (sqrtf(fmaxf(d_stats[3] / M - mu_g * mu_g, 0.f)) + LN_EPS);
    float a0 = alpha[0], a1 = alpha[1];
    float mx = fmaxf(a0, a1);
    float e0 = expf(a0 - mx), e1 = expf(a1 - mx);
    float w0 = e0 / (e0 + e1), w1 = e1 / (e0 + e1);

    int gid0 = blockIdx.x * blockDim.x + threadIdx.x;
    int gstride = gridDim.x * blockDim.x;
    for (int i = gid0; i < NN; i += gstride) d_cntw[i] = 0ULL;
    if (gid0 < SCAN_BLOCKS) d_bsum[gid0] = 0;

    float sf = 0.f, ssf = 0.f;
    const float4* x4 = (const float4*)x;
    const uint2* h2 = (const uint2*)d_h;
    const uint2* g2 = (const uint2*)d_g;
    uint2* f2 = (uint2*)d_fused;
    for (int i = gid0; i < ND4; i += gstride) {
        int c4 = i & 31;
        float4 nwh = __ldg(((const float4*)gcn_nw) + c4);
        float4 nbh = __ldg(((const float4*)gcn_nb) + c4);
        float4 nwg = __ldg(((const float4*)gat_nw) + c4);
        float4 nbg = __ldg(((const float4*)gat_nb) + c4);
        uint2 hu = h2[i], gu = g2[i];
        float4 hv = hfpair(hu.x, hu.y);
        float4 gv = hfpair(gu.x, gu.y);
        float4 xv = x4[i];
        float4 fv;
        float t, u;
        t = gelu_exact((hv.x - mu_h) * inv_h * nwh.x + nbh.x);
        u = gelu_exact((gv.x - mu_g) * inv_g * nwg.x + nbg.x);
        fv.x = w0 * (xv.x + t) + w1 * (xv.x + u);
        t = gelu_exact((hv.y - mu_h) * inv_h * nwh.y + nbh.y);
        u = gelu_exact((gv.y - mu_g) * inv_g * nwg.y + nbg.y);
        fv.y = w0 * (xv.y + t) + w1 * (xv.y + u);
        t = gelu_exact((hv.z - mu_h) * inv_h * nwh.z + nbh.z);
        u = gelu_exact((gv.z - mu_g) * inv_g * nwg.z + nbg.z);
        fv.z = w0 * (xv.z + t) + w1 * (xv.z + u);
        t = gelu_exact((hv.w - mu_h) * inv_h * nwh.w + nbh.w);
        u = gelu_exact((gv.w - mu_g) * inv_g * nwg.w + nbg.w);
        fv.w = w0 * (xv.w + t) + w1 * (xv.w + u);

        uint2 fw = pack_h4(fv);
        f2[i] = fw;
        float4 fr = hfpair(fw.x, fw.y);
        sf  += fr.x + fr.y + fr.z + fr.w;
        ssf += fr.x * fr.x + fr.y * fr.y + fr.z * fr.z + fr.w * fr.w;
    }
    #pragma unroll
    for (int o = 16; o; o >>= 1) {
        sf  += __shfl_down_sync(0xffffffffu, sf, o);
        ssf += __shfl_down_sync(0xffffffffu, ssf, o);
    }
    __shared__ float sm[2][8];
    int wid = threadIdx.x >> 5, lane = threadIdx.x & 31;
    if (lane == 0) { sm[0][wid] = sf; sm[1][wid] = ssf; }
    __syncthreads();
    if (threadIdx.x == 0) {
        float a = 0.f, b = 0.f;
        #pragma unroll
        for (int i = 0; i < 8; i++) { a += sm[0][i]; b += sm[1][i]; }
        atomicAdd(&d_stats[4], a);
        atomicAdd(&d_stats[5], b);
    }
}

// ---------------- K7: final LN + gelu -> out; re-zero stats[0..3] for next call ----------------
__global__ void out_kernel(const float* __restrict__ onw, const float* __restrict__ onb,
                           float* __restrict__ out) {
    const float M = (float)ND;
    float mu = d_stats[4] / M;
    float inv = 1.0f / (sqrtf(fmaxf(d_stats[5] / M - mu * mu, 0.f)) + LN_EPS);
    if (blockIdx.x == 0 && threadIdx.x < 4) d_stats[threadIdx.x] = 0.f;
    const uint2* f2 = (const uint2*)d_fused;
    float4* o4 = (float4*)out;
    for (int i = blockIdx.x * blockDim.x + threadIdx.x; i < ND4; i += gridDim.x * blockDim.x) {
        int c4 = i & 31;
        float4 nw = __ldg(((const float4*)onw) + c4);
        float4 nb = __ldg(((const float4*)onb) + c4);
        uint2 fu = f2[i];
        float4 fv = hfpair(fu.x, fu.y);
        float4 ov;
        ov.x = gelu_exact((fv.x - mu) * inv * nw.x + nb.x);
        ov.y = gelu_exact((fv.y - mu) * inv * nw.y + nb.y);
        ov.z = gelu_exact((fv.z - mu) * inv * nw.z + nb.z);
        ov.w = gelu_exact((fv.w - mu) * inv * nw.w + nb.w);
        o4[i] = ov;
    }
}

// ---------------- launch ----------------
extern "C" void kernel_launch(void* const* d_in, const int* in_sizes, int n_in,
                              void* d_out, int out_size) {
    const float* x      = (const float*)d_in[0];
    const int*   ei     = (const int*)d_in[1];
    const float* ew     = (const float*)d_in[2];
    const float* ea     = (const float*)d_in[3];
    const float* W_gcn  = (const float*)d_in[4];
    const float* b_gcn  = (const float*)d_in[5];
    const float* W_l    = (const float*)d_in[6];
    const float* b_l    = (const float*)d_in[7];
    const float* W_edge = (const float*)d_in[8];
    const float* att    = (const float*)d_in[9];
    const float* b_gat  = (const float*)d_in[10];
    const float* gcn_nw = (const float*)d_in[11];
    const float* gcn_nb = (const float*)d_in[12];
    const float* gat_nw = (const float*)d_in[13];
    const float* gat_nb = (const float*)d_in[14];
    const float* out_nw = (const float*)d_in[15];
    const float* out_nb = (const float*)d_in[16];
    const float* alpha  = (const float*)d_in[17];
    float* out = (float*)d_out;

    static cudaStream_t s_side = 0;
    static cudaEvent_t ev_fork = 0, ev_join = 0;
    if (!s_side) {
        cudaStreamCreateWithFlags(&s_side, cudaStreamNonBlocking);
        cudaEventCreateWithFlags(&ev_fork, cudaEventDisableTiming);
        cudaEventCreateWithFlags(&ev_join, cudaEventDisableTiming);
    }

    const int GEMM_SMEM = 2 * 128 * ASTRIDE * sizeof(float);  // 139264 B
    cudaFuncSetAttribute(gemm_tf32_kernel, cudaFuncAttributeMaxDynamicSharedMemorySize, GEMM_SMEM);

    // fork: GEMM on side stream, CSR build on main stream
    cudaEventRecord(ev_fork, 0);
    cudaStreamWaitEvent(s_side, ev_fork, 0);
    dim3 gg((NN + 127) / 128, 2);
    gemm_tf32_kernel<<<gg, 256, GEMM_SMEM, s_side>>>(x, W_gcn, W_l, b_l);
    cudaEventRecord(ev_join, s_side);

    count_kernel<<<(EE + 255) / 256, 256>>>(ei, ew);
    scan_kernel<<<SCAN_BLOCKS, 1024>>>();
    scatter_kernel<<<(EE + 255) / 256, 256>>>(ei, ew, ea);

    // join: agg needs both CSR and GEMM outputs
    cudaStreamWaitEvent(0, ev_join, 0);
    agg_kernel<<<(NN + 7) / 8, 256>>>(b_gcn, b_gat, W_edge, att);
    fuse_kernel<<<1480, 256>>>(x, gcn_nw, gcn_nb, gat_nw, gat_nb, alpha);
    out_kernel<<<1480, 256>>>(out_nw, out_nb, out);
}

// round 15
// speedup vs baseline: 1.1029x; 1.0293x over previous
#include <cuda_runtime.h>
#include <cuda_fp16.h>
#include <math.h>

#define NN   50000
#define EE   800000
#define DIMM 128
#define ND   (NN*DIMM)
#define ND4  (ND/4)
#define LN_EPS 1e-5f
#define SCAN_BLOCKS ((NN + 1023) / 1024)   // 49
#define CNT_SHIFT 44
#define W_SCALE 16777216.0f                // 2^24
#define W_MASK ((1ULL << CNT_SHIFT) - 1ULL)

// ---------------- scratch ----------------
__device__ __align__(16) __half d_xcat[2*ND];
__device__ __align__(16) __half d_h[ND];       // GCN pre-LN (fp16 storage)
__device__ __align__(16) __half d_g[ND];       // GAT pre-LN (fp16 storage)
__device__ __align__(16) __half d_fused[ND];   // fused pre-final-LN (fp16 storage)
__device__ unsigned long long d_cntw[NN];      // [count:20 | degw fixed-point:44]
__device__ int    d_rowptr[NN+1];
__device__ int    d_erank[EE];                 // per-edge rank within its dst
__device__ float  d_dis[NN];
__device__ int2   d_csr[EE];               // {src, half2(dis[src]*ew, edge_attr)}
__device__ int    d_bsum[SCAN_BLOCKS];     // 0 = not ready, else tot+1
__device__ float  d_stats[8];              // [Sh,SSh,Sg,SSg,Sf,SSf]

__device__ __forceinline__ float gelu_exact(float v) {
    return 0.5f * v * (1.0f + erff(v * 0.7071067811865475f));
}

__device__ __forceinline__ float f2tf32f(float x) {
    unsigned r;
    asm("cvt.rna.tf32.f32 %0, %1;" : "=r"(r) : "f"(x));
    return __uint_as_float(r);
}

__device__ __forceinline__ void mma_tf32(float c[4], const unsigned a[4], const unsigned b[2]) {
    asm volatile(
        "mma.sync.aligned.m16n8k8.row.col.f32.tf32.tf32.f32 "
        "{%0,%1,%2,%3},{%4,%5,%6,%7},{%8,%9},{%0,%1,%2,%3};"
        : "+f"(c[0]), "+f"(c[1]), "+f"(c[2]), "+f"(c[3])
        : "r"(a[0]), "r"(a[1]), "r"(a[2]), "r"(a[3]), "r"(b[0]), "r"(b[1]));
}

__device__ __forceinline__ float4 hfpair(unsigned a, unsigned b) {
    __half2 x = *reinterpret_cast<const __half2*>(&a);
    __half2 y = *reinterpret_cast<const __half2*>(&b);
    float2 f0 = __half22float2(x);
    float2 f1 = __half22float2(y);
    return make_float4(f0.x, f0.y, f1.x, f1.y);
}

__device__ __forceinline__ uint2 pack_h4(float4 v) {
    __half2 p01 = __floats2half2_rn(v.x, v.y);
    __half2 p23 = __floats2half2_rn(v.z, v.w);
    return make_uint2(*reinterpret_cast<unsigned*>(&p01), *reinterpret_cast<unsigned*>(&p23));
}

// ---------------- K1: fused histogram: count + weighted degree in ONE atomic ----------------
__global__ void count_kernel(const int* __restrict__ ei, const float* __restrict__ ew) {
    int e = blockIdx.x * blockDim.x + threadIdx.x;
    if (e >= EE) return;
    int dv = ei[EE + e];
    unsigned long long pack = (1ULL << CNT_SHIFT)
                            + (unsigned long long)(ew[e] * W_SCALE + 0.5f);
    unsigned long long old = atomicAdd(&d_cntw[dv], pack);
    d_erank[e] = (int)(old >> CNT_SHIFT);     // rank of this edge within its dst
}

// ---------------- K2: single-kernel scan with decoupled lookback ----------------
__global__ void __launch_bounds__(1024) scan_kernel() {
    __shared__ int wsum[32];
    __shared__ int soff;
    int t = threadIdx.x, lane = t & 31, wid = t >> 5;
    int b = blockIdx.x;
    int idx = b * 1024 + t;
    if (b == 0 && t == 0) { d_stats[4] = 0.f; d_stats[5] = 0.f; }
    unsigned long long cw = (idx < NN) ? d_cntw[idx] : 0ULL;
    int v = (int)(cw >> CNT_SHIFT);
    int incl = v;
    #pragma unroll
    for (int o = 1; o < 32; o <<= 1) {
        int u = __shfl_up_sync(0xffffffffu, incl, o);
        if (lane >= o) incl += u;
    }
    if (lane == 31) wsum[wid] = incl;
    __syncthreads();
    if (wid == 0) {
        int wv = wsum[lane];
        #pragma unroll
        for (int o = 1; o < 32; o <<= 1) {
            int u = __shfl_up_sync(0xffffffffu, wv, o);
            if (lane >= o) wv += u;
        }
        wsum[lane] = wv;
    }
    __syncthreads();
    int my_incl = (wid ? wsum[wid - 1] : 0) + incl;
    if (t == 0) atomicExch(&d_bsum[b], wsum[31] + 1);   // publish block total
    if (wid == 0) {                                     // decoupled lookback
        int acc = 0;
        for (int p = lane; p < b; p += 32) {
            int val;
            while ((val = atomicAdd(&d_bsum[p], 0)) == 0) __nanosleep(40);
            acc += val - 1;
        }
        #pragma unroll
        for (int o = 16; o; o >>= 1) acc += __shfl_down_sync(0xffffffffu, acc, o);
        if (lane == 0) soff = acc;
    }
    __syncthreads();
    if (idx == 0) d_rowptr[0] = 0;
    if (idx >= NN) return;
    d_rowptr[idx + 1] = my_incl + soff;
    float dw = (float)((double)(cw & W_MASK) * (1.0 / (double)W_SCALE));
    d_dis[idx] = (dw > 0.f) ? rsqrtf(fmaxf(dw, 1e-30f)) : 0.f;
}

// ---------------- K3: scatter edges into packed 8B CSR (atomic-free) ----------------
__global__ void scatter_kernel(const int* __restrict__ ei, const float* __restrict__ ew,
                               const float* __restrict__ ea) {
    int e = blockIdx.x * blockDim.x + threadIdx.x;
    if (e >= EE) return;
    int s = ei[e];
    int dv = ei[EE + e];
    int p = d_rowptr[dv] + d_erank[e];
    float w = d_dis[s] * ew[e];
    __half2 pk = __floats2half2_rn(w, ea[e]);
    d_csr[p] = make_int2(s, *reinterpret_cast<int*>(&pk));
}

// ---------------- K4: dual GEMM, single-term TF32 MMA, fp16 epilogue ----------------
#define ASTRIDE 136
__global__ void __launch_bounds__(256) gemm_tf32_kernel(const float* __restrict__ X,
                                                        const float* __restrict__ W0,
                                                        const float* __restrict__ W1,
                                                        const float* __restrict__ b1) {
    extern __shared__ float smem[];
    float* As = smem;                     // [128][136], tf32-rounded
    float* Ws = smem + 128 * ASTRIDE;     // [128][136], tf32-rounded
    const float* W = blockIdx.y ? W1 : W0;
    const int obase2 = blockIdx.y ? 2 : 0;

    int t = threadIdx.x;
    int row0 = blockIdx.x * 128;

    #pragma unroll
    for (int i = 0; i < 16; i++) {
        int idx = t + 256 * i;
        int r = idx >> 5;
        int c = (idx & 31) * 4;
        float4 xv = make_float4(0.f, 0.f, 0.f, 0.f);
        int grow = row0 + r;
        if (grow < NN) xv = *(const float4*)(X + grow * 128 + c);
        float4 wv = *(const float4*)(W + r * 128 + c);
        xv.x = f2tf32f(xv.x); xv.y = f2tf32f(xv.y);
        xv.z = f2tf32f(xv.z); xv.w = f2tf32f(xv.w);
        wv.x = f2tf32f(wv.x); wv.y = f2tf32f(wv.y);
        wv.z = f2tf32f(wv.z); wv.w = f2tf32f(wv.w);
        *(float4*)(As + r * ASTRIDE + c) = xv;
        *(float4*)(Ws + r * ASTRIDE + c) = wv;
    }
    __syncthreads();

    int warp = t >> 5;
    int lane = t & 31;
    int gid = lane >> 2;
    int tid = lane & 3;
    int m0 = warp * 16;

    float c[16][4];
    #pragma unroll
    for (int nt = 0; nt < 16; nt++)
        #pragma unroll
        for (int j = 0; j < 4; j++) c[nt][j] = 0.f;

    #pragma unroll 2
    for (int ks = 0; ks < 16; ks++) {
        int k0 = ks * 8;
        const float* Ap = As + (m0 + gid) * ASTRIDE + k0 + tid;
        unsigned a[4];
        a[0] = __float_as_uint(Ap[0]);
        a[1] = __float_as_uint(Ap[8 * ASTRIDE]);
        a[2] = __float_as_uint(Ap[4]);
        a[3] = __float_as_uint(Ap[8 * ASTRIDE + 4]);
        const float* Bp = Ws + (k0 + tid) * ASTRIDE + gid;
        #pragma unroll
        for (int nt = 0; nt < 16; nt++) {
            unsigned b[2];
            b[0] = __float_as_uint(Bp[nt * 8]);
            b[1] = __float_as_uint(Bp[4 * ASTRIDE + nt * 8]);
            mma_tf32(c[nt], a, b);
        }
    }

    unsigned* xcat_u = (unsigned*)d_xcat;
    int rA = row0 + m0 + gid;
    int rB = rA + 8;
    #pragma unroll
    for (int nt = 0; nt < 16; nt++) {
        int col = nt * 8 + 2 * tid;
        int q = col >> 2;
        int word = tid & 1;
        int uoff = q * 4 + obase2 + word;
        float bv0 = 0.f, bv1 = 0.f;
        if (blockIdx.y) { bv0 = __ldg(b1 + col); bv1 = __ldg(b1 + col + 1); }
        if (rA < NN) {
            __half2 pv = __float22half2_rn(make_float2(c[nt][0] + bv0, c[nt][1] + bv1));
            xcat_u[rA * 128 + uoff] = *reinterpret_cast<unsigned*>(&pv);
        }
        if (rB < NN) {
            __half2 pv = __float22half2_rn(make_float2(c[nt][2] + bv0, c[nt][3] + bv1));
            xcat_u[rB * 128 + uoff] = *reinterpret_cast<unsigned*>(&pv);
        }
    }
}

// ---------------- K5: warp-per-dst aggregation, 4 edges/iter + fused LN stats ----------------
__global__ void __launch_bounds__(256) agg_kernel(const float* __restrict__ b_gcn,
                                                  const float* __restrict__ b_gat,
                                                  const float* __restrict__ W_edge,
                                                  const float* __restrict__ att) {
    int gw = (blockIdx.x * blockDim.x + threadIdx.x) >> 5;
    int lane = threadIdx.x & 31;
    float s_h = 0.f, ss_h = 0.f, s_g = 0.f, ss_g = 0.f;

    if (gw < NN) {
        int r0 = d_rowptr[gw];
        int r1 = d_rowptr[gw + 1];
        float disd = d_dis[gw];

        const uint4* cat = (const uint4*)d_xcat;   // node row = 32 uint4
        uint4 ud = cat[gw * 32 + lane];
        float4 xld = hfpair(ud.z, ud.w);
        float4 we  = __ldg(((const float4*)W_edge) + lane);
        float4 at  = __ldg(((const float4*)att) + lane);

        float4 hacc = make_float4(0.f, 0.f, 0.f, 0.f);
        float4 acc  = make_float4(0.f, 0.f, 0.f, 0.f);
        float m = -INFINITY, dsum = 0.f;

        int p = r0;
        // 4 edges per iteration: all loads issued first, then merge
        for (; p + 3 < r1; p += 4) {
            int2 cc[4];
            #pragma unroll
            for (int j = 0; j < 4; j++) cc[j] = __ldg(&d_csr[p + j]);
            uint4 uu[4];
            #pragma unroll
            for (int j = 0; j < 4; j++) uu[j] = cat[cc[j].x * 32 + lane];

            float pl[4], ew4[4];
            float4 xl4v[4];
            #pragma unroll
            for (int j = 0; j < 4; j++) {
                float2 wp = __half22float2(*reinterpret_cast<const __half2*>(&cc[j].y));
                float cw = wp.x * disd;
                ew4[j] = cw;
                float4 xw = hfpair(uu[j].x, uu[j].y);
                float4 xl = hfpair(uu[j].z, uu[j].w);
                xl4v[j] = xl;
                hacc.x += cw * xw.x; hacc.y += cw * xw.y;
                hacc.z += cw * xw.z; hacc.w += cw * xw.w;
                float4 z;
                z.x = xld.x + xl.x + wp.y * we.x;
                z.y = xld.y + xl.y + wp.y * we.y;
                z.z = xld.z + xl.z + wp.y * we.z;
                z.w = xld.w + xl.w + wp.y * we.w;
                z.x = z.x > 0.f ? z.x : 0.2f * z.x;
                z.y = z.y > 0.f ? z.y : 0.2f * z.y;
                z.z = z.z > 0.f ? z.z : 0.2f * z.z;
                z.w = z.w > 0.f ? z.w : 0.2f * z.w;
                pl[j] = z.x * at.x + z.y * at.y + z.z * at.z + z.w * at.w;
            }
            #pragma unroll
            for (int j = 0; j < 4; j++) {
                pl[j] += __shfl_xor_sync(0xffffffffu, pl[j], 1);
                pl[j] += __shfl_xor_sync(0xffffffffu, pl[j], 2);
                pl[j] += __shfl_xor_sync(0xffffffffu, pl[j], 4);
            }
            float mn = fmaxf(fmaxf(m, fmaxf(pl[0], pl[1])), fmaxf(pl[2], pl[3]));
            float sc = __expf(m - mn);
            float ee[4];
            #pragma unroll
            for (int j = 0; j < 4; j++) ee[j] = __expf(pl[j] - mn);
            dsum = dsum * sc + ee[0] + ee[1] + ee[2] + ee[3];
            acc.x = acc.x * sc + ee[0]*xl4v[0].x + ee[1]*xl4v[1].x + ee[2]*xl4v[2].x + ee[3]*xl4v[3].x;
            acc.y = acc.y * sc + ee[0]*xl4v[0].y + ee[1]*xl4v[1].y + ee[2]*xl4v[2].y + ee[3]*xl4v[3].y;
            acc.z = acc.z * sc + ee[0]*xl4v[0].z + ee[1]*xl4v[1].z + ee[2]*xl4v[2].z + ee[3]*xl4v[3].z;
            acc.w = acc.w * sc + ee[0]*xl4v[0].w + ee[1]*xl4v[1].w + ee[2]*xl4v[2].w + ee[3]*xl4v[3].w;
            m = mn;
        }
        // tail: 0..3 remaining edges
        for (; p < r1; ++p) {
            int2 ce = __ldg(&d_csr[p]);
            float2 wea = __half22float2(*reinterpret_cast<const __half2*>(&ce.y));
            float cw  = wea.x * disd;
            float eav = wea.y;
            uint4 us = cat[ce.x * 32 + lane];
            float4 xws = hfpair(us.x, us.y);
            float4 xls = hfpair(us.z, us.w);

            hacc.x += cw * xws.x; hacc.y += cw * xws.y;
            hacc.z += cw * xws.z; hacc.w += cw * xws.w;

            float4 z;
            z.x = xld.x + xls.x + eav * we.x;
            z.y = xld.y + xls.y + eav * we.y;
            z.z = xld.z + xls.z + eav * we.z;
            z.w = xld.w + xls.w + eav * we.w;
            z.x = z.x > 0.f ? z.x : 0.2f * z.x;
            z.y = z.y > 0.f ? z.y : 0.2f * z.y;
            z.z = z.z > 0.f ? z.z : 0.2f * z.z;
            z.w = z.w > 0.f ? z.w : 0.2f * z.w;
            float part = z.x * at.x + z.y * at.y + z.z * at.z + z.w * at.w;
            part += __shfl_xor_sync(0xffffffffu, part, 1);
            part += __shfl_xor_sync(0xffffffffu, part, 2);
            part += __shfl_xor_sync(0xffffffffu, part, 4);

            float mn = fmaxf(m, part);
            float sc = __expf(m - mn);
            float pe = __expf(part - mn);
            dsum = dsum * sc + pe;
            acc.x = acc.x * sc + pe * xls.x;
            acc.y = acc.y * sc + pe * xls.y;
            acc.z = acc.z * sc + pe * xls.z;
            acc.w = acc.w * sc + pe * xls.w;
            m = mn;
        }

        float inv = 1.0f / (dsum + 1e-16f);
        float4 bc = __ldg(((const float4*)b_gcn) + lane);
        float4 bg = __ldg(((const float4*)b_gat) + lane);
        float4 ho = make_float4(hacc.x + bc.x, hacc.y + bc.y, hacc.z + bc.z, hacc.w + bc.w);
        float4 go = make_float4(acc.x * inv + bg.x, acc.y * inv + bg.y,
                                acc.z * inv + bg.z, acc.w * inv + bg.w);

        uint2 hw = pack_h4(ho);
        uint2 gww = pack_h4(go);
        ((uint2*)d_h)[gw * 32 + lane] = hw;
        ((uint2*)d_g)[gw * 32 + lane] = gww;
        float4 hr = hfpair(hw.x, hw.y);
        float4 gr = hfpair(gww.x, gww.y);

        s_h  = hr.x + hr.y + hr.z + hr.w;
        ss_h = hr.x * hr.x + hr.y * hr.y + hr.z * hr.z + hr.w * hr.w;
        s_g  = gr.x + gr.y + gr.z + gr.w;
        ss_g = gr.x * gr.x + gr.y * gr.y + gr.z * gr.z + gr.w * gr.w;
    }

    #pragma unroll
    for (int o = 16; o; o >>= 1) {
        s_h  += __shfl_down_sync(0xffffffffu, s_h, o);
        ss_h += __shfl_down_sync(0xffffffffu, ss_h, o);
        s_g  += __shfl_down_sync(0xffffffffu, s_g, o);
        ss_g += __shfl_down_sync(0xffffffffu, ss_g, o);
    }
    __shared__ float sm[4][8];
    int wid = threadIdx.x >> 5;
    if (lane == 0) { sm[0][wid] = s_h; sm[1][wid] = ss_h; sm[2][wid] = s_g; sm[3][wid] = ss_g; }
    __syncthreads();
    if (threadIdx.x == 0) {
        float a = 0.f, b = 0.f, cc = 0.f, d = 0.f;
        #pragma unroll
        for (int i = 0; i < 8; i++) { a += sm[0][i]; b += sm[1][i]; cc += sm[2][i]; d += sm[3][i]; }
        atomicAdd(&d_stats[0], a);
        atomicAdd(&d_stats[1], b);
        atomicAdd(&d_stats[2], cc);
        atomicAdd(&d_stats[3], d);
    }
}

// ---------------- K6: LN+gelu both branches, residual, fuse; stats of fused ----------------
// also re-zeroes d_cntw/d_bsum for the next call
__global__ void fuse_kernel(const float* __restrict__ x,
                            const float* __restrict__ gcn_nw, const float* __restrict__ gcn_nb,
                            const float* __restrict__ gat_nw, const float* __restrict__ gat_nb,
                            const float* __restrict__ alpha) {
    const float M = (float)ND;
    float mu_h = d_stats[0] / M;
    float inv_h = 1.0f / (sqrtf(fmaxf(d_stats[1] / M - mu_h * mu_h, 0.f)) + LN_EPS);
    float mu_g = d_stats[2] / M;
    float inv_g = 1.0f / (sqrtf(fmaxf(d_stats[3] / M - mu_g * mu_g, 0.f)) + LN_EPS);
    float a0 = alpha[0], a1 = alpha[1];
    float mx = fmaxf(a0, a1);
    float e0 = expf(a0 - mx), e1 = expf(a1 - mx);
    float w0 = e0 / (e0 + e1), w1 = e1 / (e0 + e1);

    int gid0 = blockIdx.x * blockDim.x + threadIdx.x;
    int gstride = gridDim.x * blockDim.x;
    for (int i = gid0; i < NN; i += gstride) d_cntw[i] = 0ULL;
    if (gid0 < SCAN_BLOCKS) d_bsum[gid0] = 0;

    float sf = 0.f, ssf = 0.f;
    const float4* x4 = (const float4*)x;
    const uint2* h2 = (const uint2*)d_h;
    const uint2* g2 = (const uint2*)d_g;
    uint2* f2 = (uint2*)d_fused;
    for (int i = gid0; i < ND4; i += gstride) {
        int c4 = i & 31;
        float4 nwh = __ldg(((const float4*)gcn_nw) + c4);
        float4 nbh = __ldg(((const float4*)gcn_nb) + c4);
        float4 nwg = __ldg(((const float4*)gat_nw) + c4);
        float4 nbg = __ldg(((const float4*)gat_nb) + c4);
        uint2 hu = h2[i], gu = g2[i];
        float4 hv = hfpair(hu.x, hu.y);
        float4 gv = hfpair(gu.x, gu.y);
        float4 xv = x4[i];
        float4 fv;
        float t, u;
        t = gelu_exact((hv.x - mu_h) * inv_h * nwh.x + nbh.x);
        u = gelu_exact((gv.x - mu_g) * inv_g * nwg.x + nbg.x);
        fv.x = w0 * (xv.x + t) + w1 * (xv.x + u);
        t = gelu_exact((hv.y - mu_h) * inv_h * nwh.y + nbh.y);
        u = gelu_exact((gv.y - mu_g) * inv_g * nwg.y + nbg.y);
        fv.y = w0 * (xv.y + t) + w1 * (xv.y + u);
        t = gelu_exact((hv.z - mu_h) * inv_h * nwh.z + nbh.z);
        u = gelu_exact((gv.z - mu_g) * inv_g * nwg.z + nbg.z);
        fv.z = w0 * (xv.z + t) + w1 * (xv.z + u);
        t = gelu_exact((hv.w - mu_h) * inv_h * nwh.w + nbh.w);
        u = gelu_exact((gv.w - mu_g) * inv_g * nwg.w + nbg.w);
        fv.w = w0 * (xv.w + t) + w1 * (xv.w + u);

        uint2 fw = pack_h4(fv);
        f2[i] = fw;
        float4 fr = hfpair(fw.x, fw.y);
        sf  += fr.x + fr.y + fr.z + fr.w;
        ssf += fr.x * fr.x + fr.y * fr.y + fr.z * fr.z + fr.w * fr.w;
    }
    #pragma unroll
    for (int o = 16; o; o >>= 1) {
        sf  += __shfl_down_sync(0xffffffffu, sf, o);
        ssf += __shfl_down_sync(0xffffffffu, ssf, o);
    }
    __shared__ float sm[2][8];
    int wid = threadIdx.x >> 5, lane = threadIdx.x & 31;
    if (lane == 0) { sm[0][wid] = sf; sm[1][wid] = ssf; }
    __syncthreads();
    if (threadIdx.x == 0) {
        float a = 0.f, b = 0.f;
        #pragma unroll
        for (int i = 0; i < 8; i++) { a += sm[0][i]; b += sm[1][i]; }
        atomicAdd(&d_stats[4], a);
        atomicAdd(&d_stats[5], b);
    }
}

// ---------------- K7: final LN + gelu -> out; re-zero stats[0..3] for next call ----------------
__global__ void out_kernel(const float* __restrict__ onw, const float* __restrict__ onb,
                           float* __restrict__ out) {
    const float M = (float)ND;
    float mu = d_stats[4] / M;
    float inv = 1.0f / (sqrtf(fmaxf(d_stats[5] / M - mu * mu, 0.f)) + LN_EPS);
    if (blockIdx.x == 0 && threadIdx.x < 4) d_stats[threadIdx.x] = 0.f;
    const uint2* f2 = (const uint2*)d_fused;
    float4* o4 = (float4*)out;
    for (int i = blockIdx.x * blockDim.x + threadIdx.x; i < ND4; i += gridDim.x * blockDim.x) {
        int c4 = i & 31;
        float4 nw = __ldg(((const float4*)onw) + c4);
        float4 nb = __ldg(((const float4*)onb) + c4);
        uint2 fu = f2[i];
        float4 fv = hfpair(fu.x, fu.y);
        float4 ov;
        ov.x = gelu_exact((fv.x - mu) * inv * nw.x + nb.x);
        ov.y = gelu_exact((fv.y - mu) * inv * nw.y + nb.y);
        ov.z = gelu_exact((fv.z - mu) * inv * nw.z + nb.z);
        ov.w = gelu_exact((fv.w - mu) * inv * nw.w + nb.w);
        o4[i] = ov;
    }
}

// ---------------- launch ----------------
extern "C" void kernel_launch(void* const* d_in, const int* in_sizes, int n_in,
                              void* d_out, int out_size) {
    const float* x      = (const float*)d_in[0];
    const int*   ei     = (const int*)d_in[1];
    const float* ew     = (const float*)d_in[2];
    const float* ea     = (const float*)d_in[3];
    const float* W_gcn  = (const float*)d_in[4];
    const float* b_gcn  = (const float*)d_in[5];
    const float* W_l    = (const float*)d_in[6];
    const float* b_l    = (const float*)d_in[7];
    const float* W_edge = (const float*)d_in[8];
    const float* att    = (const float*)d_in[9];
    const float* b_gat  = (const float*)d_in[10];
    const float* gcn_nw = (const float*)d_in[11];
    const float* gcn_nb = (const float*)d_in[12];
    const float* gat_nw = (const float*)d_in[13];
    const float* gat_nb = (const float*)d_in[14];
    const float* out_nw = (const float*)d_in[15];
    const float* out_nb = (const float*)d_in[16];
    const float* alpha  = (const float*)d_in[17];
    float* out = (float*)d_out;

    static cudaStream_t s_side = 0;
    static cudaEvent_t ev_fork = 0, ev_join = 0;
    if (!s_side) {
        cudaStreamCreateWithFlags(&s_side, cudaStreamNonBlocking);
        cudaEventCreateWithFlags(&ev_fork, cudaEventDisableTiming);
        cudaEventCreateWithFlags(&ev_join, cudaEventDisableTiming);
    }

    const int GEMM_SMEM = 2 * 128 * ASTRIDE * sizeof(float);  // 139264 B
    cudaFuncSetAttribute(gemm_tf32_kernel, cudaFuncAttributeMaxDynamicSharedMemorySize, GEMM_SMEM);

    // fork: GEMM on side stream, CSR build on main stream
    cudaEventRecord(ev_fork, 0);
    cudaStreamWaitEvent(s_side, ev_fork, 0);
    dim3 gg((NN + 127) / 128, 2);
    gemm_tf32_kernel<<<gg, 256, GEMM_SMEM, s_side>>>(x, W_gcn, W_l, b_l);
    cudaEventRecord(ev_join, s_side);

    count_kernel<<<(EE + 255) / 256, 256>>>(ei, ew);
    scan_kernel<<<SCAN_BLOCKS, 1024>>>();
    scatter_kernel<<<(EE + 255) / 256, 256>>>(ei, ew, ea);

    // join: agg needs both CSR and GEMM outputs
    cudaStreamWaitEvent(0, ev_join, 0);
    agg_kernel<<<(NN + 7) / 8, 256>>>(b_gcn, b_gat, W_edge, att);
    fuse_kernel<<<1480, 256>>>(x, gcn_nw, gcn_nb, gat_nw, gat_nb, alpha);
    out_kernel<<<1480, 256>>>(out_nw, out_nb, out);
}